// round 13
// baseline (speedup 1.0000x reference)
#include <cuda_runtime.h>
#include <math.h>

// Problem constants
#define B_    256
#define I_    1152
#define J_    10
#define DIN   8
#define DOUT  16
#define KDIM  (I_*DIN)     // 9216  (contraction dim of S-GEMM, rows of G)
#define NDIM  (J_*DOUT)    // 160   (j*16+d)
#define SPLITK 36
#define KCHUNK (KDIM/SPLITK)  // 256
#define KK    32              // smem k-tile

// ---- scratch (__device__ globals: allocation-free rule) ----
__device__ float g_Wt[KDIM*NDIM];           // W rearranged: Wt[ik][jd] = W[i,j,d,k]   (5.9 MB)
__device__ float g_P [SPLITK*B_*NDIM];      // split-K partials of s                   (5.9 MB)
__device__ float g_G [KDIM*NDIM];           // G[ik][jd] = sum_b x[b,ik]*s[b,jd]       (5.9 MB)
__device__ float g_s [B_*NDIM];             // squashed s (iterations 1,2)
__device__ float g_b [I_*J_];               // routing logits
__device__ float g_c [I_*J_];               // softmax(b) coupling coefficients

// ---------------------------------------------------------------------------
// init: b = 0, c = 1/J (softmax of zeros) — must run every launch (graph replay)
__global__ void k_init() {
    int t = blockIdx.x*256 + threadIdx.x;
    if (t < I_*J_) { g_b[t] = 0.0f; g_c[t] = 0.1f; }
}

// ---------------------------------------------------------------------------
// rearrange W[I,J,DOUT,DIN] -> Wt[ik][jd]  (run once per launch)
__global__ void k_wt(const float* __restrict__ W) {
    int idx = blockIdx.x*256 + threadIdx.x;
    if (idx >= KDIM*NDIM) return;
    int ik = idx / NDIM, jd = idx - ik*NDIM;
    int i = ik >> 3, k = ik & 7;
    int j = jd >> 4, d = jd & 15;
    g_Wt[idx] = W[((i*J_ + j)*DOUT + d)*DIN + k];
}

// ---------------------------------------------------------------------------
// S-GEMM: P[sp][m][n] = sum_{k in split sp} x[m][k] * c[k>>3][n>>4] * Wt[k][n]
// M=256, N=160, K=9216. grid (4 m-tiles, 36 splits) = 144 blocks, 256 thr.
// micro-tile per thread: 4 (m) x 10 (n, stride 16 so q == j).
__global__ __launch_bounds__(256) void k_sgemm(const float* __restrict__ x) {
    __shared__ float Xs[KK*65];     // [c][r], pad 65 -> conflict-free transpose store
    __shared__ float Ws[KK*NDIM];   // [kk][n]

    const int tid = threadIdx.x;
    const int tx  = tid & 15;       // n-thread
    const int ty  = tid >> 4;       // m-thread
    const int m0  = blockIdx.x * 64;
    const int kbase = blockIdx.y * KCHUNK;

    float acc[4][10];
#pragma unroll
    for (int r = 0; r < 4; ++r)
#pragma unroll
        for (int q = 0; q < 10; ++q) acc[r][q] = 0.0f;

    for (int kc = 0; kc < KCHUNK; kc += KK) {
        const int k0 = kbase + kc;
        // load X tile 64(m) x 32(k), store transposed Xs[k][m]
#pragma unroll
        for (int e = tid; e < 64*KK; e += 256) {
            int r = e >> 5, c = e & 31;                 // coalesced along k
            Xs[c*65 + r] = x[(m0 + r)*KDIM + k0 + c];
        }
        // load Wt tile 32(k) x 160(n), scaled by coupling c[i][j]
#pragma unroll
        for (int e = tid; e < KK*NDIM; e += 256) {
            int kk = e / NDIM, n = e - kk*NDIM;         // coalesced along n
            int ik = k0 + kk;
            float cv = g_c[(ik >> 3)*J_ + (n >> 4)];
            Ws[kk*NDIM + n] = g_Wt[ik*NDIM + n] * cv;
        }
        __syncthreads();
#pragma unroll 4
        for (int kk = 0; kk < KK; ++kk) {
            float xv[4], wv[10];
#pragma unroll
            for (int r = 0; r < 4; ++r) xv[r] = Xs[kk*65 + ty*4 + r];
#pragma unroll
            for (int q = 0; q < 10; ++q) wv[q] = Ws[kk*NDIM + tx + 16*q];
#pragma unroll
            for (int r = 0; r < 4; ++r)
#pragma unroll
                for (int q = 0; q < 10; ++q) acc[r][q] += xv[r]*wv[q];
        }
        __syncthreads();
    }

    float* P = g_P + blockIdx.y*(B_*NDIM);
#pragma unroll
    for (int r = 0; r < 4; ++r) {
        int m = m0 + ty*4 + r;
#pragma unroll
        for (int q = 0; q < 10; ++q)
            P[m*NDIM + tx + 16*q] = acc[r][q];
    }
}

// ---------------------------------------------------------------------------
// reduce split-K partials + squash per (b, j) over the 16-dim capsule vector.
// grid 256 (b), 160 threads (jd). 16-lane groups align with warps (160 = 5 warps).
__global__ void k_redsquash(float* __restrict__ out, int use_out) {
    const int b  = blockIdx.x;
    const int jd = threadIdx.x;
    float v = 0.0f;
#pragma unroll
    for (int sp = 0; sp < SPLITK; ++sp)
        v += g_P[sp*(B_*NDIM) + b*NDIM + jd];

    float sq = v*v;
    sq += __shfl_xor_sync(0xffffffffu, sq, 1, 16);
    sq += __shfl_xor_sync(0xffffffffu, sq, 2, 16);
    sq += __shfl_xor_sync(0xffffffffu, sq, 4, 16);
    sq += __shfl_xor_sync(0xffffffffu, sq, 8, 16);   // sq = |s_{b,j}|^2
    float l2 = sqrtf(sq);
    float f  = l2 / (1.0f + sq);                      // squash factor
    float res = v * f;
    if (use_out) out[b*NDIM + jd] = res;
    else         g_s[b*NDIM + jd] = res;
}

// ---------------------------------------------------------------------------
// G-GEMM: G[m=ik][n=jd] = sum_{b} x[b][ik] * s[b][jd].  M=9216, N=160, K=256.
// grid 144 blocks (64-row m-tiles), 256 threads, same 4x10 micro-tile.
__global__ __launch_bounds__(256) void k_ggemm(const float* __restrict__ x) {
    __shared__ float As[KK*64];     // [kb][m]  (natural layout: x is [b][ik])
    __shared__ float Ss[KK*NDIM];   // [kb][n]

    const int tid = threadIdx.x;
    const int tx  = tid & 15;
    const int ty  = tid >> 4;
    const int m0  = blockIdx.x * 64;

    float acc[4][10];
#pragma unroll
    for (int r = 0; r < 4; ++r)
#pragma unroll
        for (int q = 0; q < 10; ++q) acc[r][q] = 0.0f;

    for (int k0 = 0; k0 < B_; k0 += KK) {
#pragma unroll
        for (int e = tid; e < KK*64; e += 256) {
            int kk = e >> 6, mm = e & 63;               // coalesced along ik
            As[kk*64 + mm] = x[(k0 + kk)*KDIM + m0 + mm];
        }
#pragma unroll
        for (int e = tid; e < KK*NDIM; e += 256) {
            int kk = e / NDIM, n = e - kk*NDIM;
            Ss[kk*NDIM + n] = g_s[(k0 + kk)*NDIM + n];
        }
        __syncthreads();
#pragma unroll 4
        for (int kk = 0; kk < KK; ++kk) {
            float xv[4], sv[10];
#pragma unroll
            for (int r = 0; r < 4; ++r) xv[r] = As[kk*64 + ty*4 + r];
#pragma unroll
            for (int q = 0; q < 10; ++q) sv[q] = Ss[kk*NDIM + tx + 16*q];
#pragma unroll
            for (int r = 0; r < 4; ++r)
#pragma unroll
                for (int q = 0; q < 10; ++q) acc[r][q] += xv[r]*sv[q];
        }
        __syncthreads();
    }
#pragma unroll
    for (int r = 0; r < 4; ++r) {
        int m = m0 + ty*4 + r;
#pragma unroll
        for (int q = 0; q < 10; ++q)
            g_G[m*NDIM + tx + 16*q] = acc[r][q];
    }
}

// ---------------------------------------------------------------------------
// b-update + softmax -> next c.
// block per i (1152 blocks), warp per j (10 warps). Each warp computes
// delta[i,j] = sum_{k,d} W[i,j,d,k] * G[(i*8+k)][j*16+d], then thread 0 does
// the 10-way softmax over j.
__global__ __launch_bounds__(320) void k_bupdate(const float* __restrict__ W) {
    const int i    = blockIdx.x;
    const int j    = threadIdx.x >> 5;
    const int lane = threadIdx.x & 31;

    const float* Wij = W + ((i*J_ + j)*DOUT)*DIN;    // 128 contiguous floats [d][k]
    float ssum = 0.0f;
#pragma unroll
    for (int t = lane; t < 128; t += 32) {
        int k = t >> 4, d = t & 15;
        ssum += Wij[d*DIN + k] * g_G[(i*DIN + k)*NDIM + j*DOUT + d];
    }
#pragma unroll
    for (int o = 16; o > 0; o >>= 1)
        ssum += __shfl_xor_sync(0xffffffffu, ssum, o);

    __shared__ float dj[J_];
    if (lane == 0) dj[j] = ssum;
    __syncthreads();

    if (threadIdx.x == 0) {
        float bb[J_];
        float mx = -1e30f;
#pragma unroll
        for (int jj = 0; jj < J_; ++jj) {
            bb[jj] = g_b[i*J_ + jj] + dj[jj];
            g_b[i*J_ + jj] = bb[jj];
            mx = fmaxf(mx, bb[jj]);
        }
        float sum = 0.0f;
#pragma unroll
        for (int jj = 0; jj < J_; ++jj) { bb[jj] = expf(bb[jj] - mx); sum += bb[jj]; }
        float inv = 1.0f / sum;
#pragma unroll
        for (int jj = 0; jj < J_; ++jj) g_c[i*J_ + jj] = bb[jj] * inv;
    }
}

// ---------------------------------------------------------------------------
extern "C" void kernel_launch(void* const* d_in, const int* in_sizes, int n_in,
                              void* d_out, int out_size) {
    const float* x = (const float*)d_in[0];   // [256, 1152, 8]
    const float* W = (const float*)d_in[1];   // [1152, 10, 16, 8]
    float* out = (float*)d_out;               // [256, 10, 16]

    k_init<<<(I_*J_ + 255)/256, 256>>>();
    k_wt  <<<(KDIM*NDIM + 255)/256, 256>>>(W);

    for (int iter = 0; iter < 3; ++iter) {
        k_sgemm<<<dim3(4, SPLITK), 256>>>(x);
        k_redsquash<<<B_, NDIM>>>(out, iter == 2 ? 1 : 0);
        if (iter < 2) {
            k_ggemm<<<KDIM/64, 256>>>(x);
            k_bupdate<<<I_, 320>>>(W);
        }
    }
}